// round 11
// baseline (speedup 1.0000x reference)
#include <cuda_runtime.h>
#include <cuda_bf16.h>
#include <math.h>

// Problem constants (B=2, N=2048, H=64, EPS=0.01)
#define HN 64
#define EPS2f 0.0001f

// Table over d2 in [~9.92e-5, 4096], indexed by float bit pattern.
// BASE aligned to 1<<SHIFT; 2^(23-SHIFT)=64 samples per binade.
#define TAB_SHIFT 17
#define TAB_BASE  0x38D00000        // 9.918e-5f  (< 1e-4 = EPS^2: no lower clamp needed)
#define TAB_TOP   0x45800000        // 4096.0f
#define TAB_ENTRIES ((TAB_TOP - TAB_BASE) >> TAB_SHIFT)   // 1624

__device__ float2 g_tab[TAB_ENTRIES];   // (intercept c0 = v0 - x0*s, slope s)

// ---------------------------------------------------------------------------
// Kernel 1 (fused): evaluate MLP m(d2) at 17 grid points per block, pack
// (intercept, slope) for 16 table entries, and zero the output buffer.
// 288 threads = 18 slots x 16 lanes. Slot p (0..16) computes point base+p;
// slot 17 duplicates slot 16 (keeps warp 8 converged for the shfl reduce).
//   phase 1: h1[p][q*4..q*4+4) into smem (padded stride 68)
//   phase 2: float4 GEMV slice over columns [q*4, q*4+4)
//   phase 3: relu + W3 dot, 16-lane shfl reduce, q==0 writes sm[p]
//   phase 4: threads 0..15 compute slope from sm[t], sm[t+1], write g_tab.
// ---------------------------------------------------------------------------
#define PPB 16
#define H1S 68   // padded h1 row stride
#define BT  288

__global__ __launch_bounds__(BT)
void build_table_kernel(const float* __restrict__ W1, const float* __restrict__ b1,
                        const float* __restrict__ W2, const float* __restrict__ b2,
                        const float* __restrict__ W3, const float* __restrict__ b3,
                        float* __restrict__ out, int out_n)
{
    __shared__ float sW2[HN * HN];
    __shared__ float sW1a[HN], sW1b[HN], sb1[HN], sb2[HN], sW3[HN];
    __shared__ float sh1[17][H1S];
    __shared__ float sm[18];

    const int tid = threadIdx.x;

    // zero the harness-poisoned output (102 blocks * 288 threads >= 12288)
    {
        int g = blockIdx.x * BT + tid;
        if (g < out_n) out[g] = 0.0f;
    }

    // load W2 (16 KB) vectorized
    {
        const float4* W24 = (const float4*)W2;
        float4* sW24 = (float4*)sW2;
#pragma unroll
        for (int t = tid; t < HN * HN / 4; t += BT) sW24[t] = W24[t];
    }
    if (tid < HN) {
        sW1a[tid] = W1[tid];        // W1[0][k]
        sW1b[tid] = W1[HN + tid];   // W1[1][k]
        sb1[tid]  = b1[tid];
        sb2[tid]  = b2[tid];
        sW3[tid]  = W3[tid];
    }
    __syncthreads();

    const int p  = tid >> 4;             // slot 0..17
    const int q  = tid & 15;             // column quarter 0..15
    const int pp = min(p, 16);           // slot 17 duplicates 16
    const int base = blockIdx.x * PPB;
    const int kc = min(base + pp, TAB_ENTRIES);

    const float d2   = __int_as_float(TAB_BASE + (kc << TAB_SHIFT));
    const float dist = sqrtf(d2);
    const float invc = 1.0f / (d2 * dist);

    // phase 1: h1 for this point's a-range [q*4, q*4+4)
    if (p < 17) {
        const int a0 = q * 4;
        float4 h;
        h.x = fmaxf(fmaf(dist, sW1a[a0 + 0], fmaf(invc, sW1b[a0 + 0], sb1[a0 + 0])), 0.0f);
        h.y = fmaxf(fmaf(dist, sW1a[a0 + 1], fmaf(invc, sW1b[a0 + 1], sb1[a0 + 1])), 0.0f);
        h.z = fmaxf(fmaf(dist, sW1a[a0 + 2], fmaf(invc, sW1b[a0 + 2], sb1[a0 + 2])), 0.0f);
        h.w = fmaxf(fmaf(dist, sW1a[a0 + 3], fmaf(invc, sW1b[a0 + 3], sb1[a0 + 3])), 0.0f);
        *(float4*)&sh1[p][a0] = h;
    }
    __syncthreads();

    // phase 2: GEMV slice, columns [c0, c0+4)
    const int c0 = q * 4;
    float ax = 0.f, ay = 0.f, az = 0.f, aw = 0.f;
#pragma unroll 8
    for (int a = 0; a < HN; a++) {
        float h = sh1[pp][a];
        float4 w = *(const float4*)&sW2[a * HN + c0];
        ax = fmaf(h, w.x, ax);
        ay = fmaf(h, w.y, ay);
        az = fmaf(h, w.z, az);
        aw = fmaf(h, w.w, aw);
    }

    // phase 3: bias + relu + W3 dot, reduce over 16 lanes
    float m = fmaxf(ax + sb2[c0 + 0], 0.0f) * sW3[c0 + 0]
            + fmaxf(ay + sb2[c0 + 1], 0.0f) * sW3[c0 + 1]
            + fmaxf(az + sb2[c0 + 2], 0.0f) * sW3[c0 + 2]
            + fmaxf(aw + sb2[c0 + 3], 0.0f) * sW3[c0 + 3];
    m += __shfl_xor_sync(0xffffffffu, m, 1);
    m += __shfl_xor_sync(0xffffffffu, m, 2);
    m += __shfl_xor_sync(0xffffffffu, m, 4);
    m += __shfl_xor_sync(0xffffffffu, m, 8);

    if (q == 0 && p < 17)
        sm[p] = m + __ldg(b3);
    __syncthreads();

    // phase 4: pack 16 entries of this block
    if (tid < PPB) {
        int e = base + tid;
        if (e < TAB_ENTRIES) {
            float x0 = __int_as_float(TAB_BASE + (e << TAB_SHIFT));
            float x1 = __int_as_float(TAB_BASE + ((e + 1) << TAB_SHIFT));
            float v0 = sm[tid];
            float v1 = sm[tid + 1];
            float s  = (v1 - v0) / (x1 - x0);
            g_tab[e] = make_float2(fmaf(-x0, s, v0), s);   // m(d2) = c0 + d2*s
        }
    }
}

// ---------------------------------------------------------------------------
// Kernel 2: tiled all-pairs force accumulation.
//   acc_i = sum_j m(d2_ij) * (pos_j - pos_i)     (j==i term is exactly 0)
// JC=32 -> 2048 blocks -> ~55 warps/SM (86% occ) for latency hiding.
// Table gather via __ldg (13 KB table is L1-resident).
// ---------------------------------------------------------------------------
#define IT 128
#define JC 32

__global__ __launch_bounds__(IT)
void forces_kernel(const float* __restrict__ pos, float* __restrict__ out, int N)
{
    const int b  = blockIdx.z;
    const int i  = blockIdx.y * IT + threadIdx.x;
    const int j0 = blockIdx.x * JC;
    const float* p = pos + (size_t)b * N * 3;

    __shared__ float4 sj[JC];
    if (threadIdx.x < JC) {
        int j = j0 + threadIdx.x;
        sj[threadIdx.x] = make_float4(p[j * 3 + 0], p[j * 3 + 1], p[j * 3 + 2], 0.0f);
    }
    __syncthreads();

    const float xi = p[i * 3 + 0];
    const float yi = p[i * 3 + 1];
    const float zi = p[i * 3 + 2];

    float ax = 0.0f, ay = 0.0f, az = 0.0f;

#pragma unroll
    for (int t = 0; t < JC; t++) {
        float4 pj = sj[t];
        float dx = pj.x - xi;
        float dy = pj.y - yi;
        float dz = pj.z - zi;
        float d2 = fmaf(dx, dx, fmaf(dy, dy, fmaf(dz, dz, EPS2f)));

        // d2 >= EPS^2 > table base, so only the upper clamp is needed
        int bits = min(__float_as_int(d2), (int)TAB_TOP - 1);
        float2 ts = __ldg(&g_tab[(unsigned)(bits - (int)TAB_BASE) >> TAB_SHIFT]);
        float m = fmaf(d2, ts.y, ts.x);

        ax = fmaf(m, dx, ax);
        ay = fmaf(m, dy, ay);
        az = fmaf(m, dz, az);
    }

    float* o = out + ((size_t)b * N + i) * 3;
    atomicAdd(o + 0, ax);
    atomicAdd(o + 1, ay);
    atomicAdd(o + 2, az);
}

// ---------------------------------------------------------------------------
// Launch
// ---------------------------------------------------------------------------
extern "C" void kernel_launch(void* const* d_in, const int* in_sizes, int n_in,
                              void* d_out, int out_size)
{
    const float* pos = (const float*)d_in[0];
    const float* W1  = (const float*)d_in[1];
    const float* b1  = (const float*)d_in[2];
    const float* W2  = (const float*)d_in[3];
    const float* b2  = (const float*)d_in[4];
    const float* W3  = (const float*)d_in[5];
    const float* b3  = (const float*)d_in[6];
    float* out = (float*)d_out;

    const int N = 2048;
    const int B = in_sizes[0] / (N * 3);   // = 2

    // 1) build m(d2) table + pack (intercept, slope) + zero output, one kernel
    {
        int blocks = (TAB_ENTRIES + PPB - 1) / PPB;   // 102
        build_table_kernel<<<blocks, BT>>>(W1, b1, W2, b2, W3, b3, out, out_size);
    }
    // 2) main all-pairs accumulation
    {
        dim3 grid(N / JC, N / IT, B);
        forces_kernel<<<grid, IT>>>(pos, out, N);
    }
}

// round 12
// speedup vs baseline: 1.1345x; 1.1345x over previous
#include <cuda_runtime.h>
#include <cuda_bf16.h>
#include <math.h>

// Problem constants (B=2, N=2048, H=64, EPS=0.01)
#define HN 64
#define EPS2f 0.0001f

// Table over d2 in [~9.92e-5, 4096], indexed by float bit pattern.
// BASE aligned to 1<<SHIFT; 2^(23-SHIFT)=32 samples per binade.
#define TAB_SHIFT 18
#define TAB_BASE  0x38D00000        // 9.918e-5f  (< 1e-4 = EPS^2: no lower clamp needed)
#define TAB_TOP   0x45800000        // 4096.0f
#define TAB_ENTRIES ((TAB_TOP - TAB_BASE) >> TAB_SHIFT)   // 812

__device__ float2 g_tab[TAB_ENTRIES];   // (intercept c0 = v0 - x0*s, slope s)

// ---------------------------------------------------------------------------
// Kernel 1 (fused): evaluate MLP m(d2) at 17 grid points per block, pack
// (intercept, slope) for 16 table entries, and zero the output buffer.
// 288 threads = 18 slots x 16 lanes. Slot p (0..16) computes point base+p;
// slot 17 duplicates slot 16 (keeps warp 8 converged for the shfl reduce).
// ---------------------------------------------------------------------------
#define PPB 16
#define H1S 68   // padded h1 row stride
#define BT  288

__global__ __launch_bounds__(BT)
void build_table_kernel(const float* __restrict__ W1, const float* __restrict__ b1,
                        const float* __restrict__ W2, const float* __restrict__ b2,
                        const float* __restrict__ W3, const float* __restrict__ b3,
                        float* __restrict__ out, int out_n)
{
    __shared__ float sW2[HN * HN];
    __shared__ float sW1a[HN], sW1b[HN], sb1[HN], sb2[HN], sW3[HN];
    __shared__ float sh1[17][H1S];
    __shared__ float sm[18];

    const int tid = threadIdx.x;

    // zero the harness-poisoned output (51 blocks * 288 threads >= 12288)
    {
        int g = blockIdx.x * BT + tid;
        if (g < out_n) out[g] = 0.0f;
    }

    // load W2 (16 KB) vectorized
    {
        const float4* W24 = (const float4*)W2;
        float4* sW24 = (float4*)sW2;
#pragma unroll
        for (int t = tid; t < HN * HN / 4; t += BT) sW24[t] = W24[t];
    }
    if (tid < HN) {
        sW1a[tid] = W1[tid];        // W1[0][k]
        sW1b[tid] = W1[HN + tid];   // W1[1][k]
        sb1[tid]  = b1[tid];
        sb2[tid]  = b2[tid];
        sW3[tid]  = W3[tid];
    }
    __syncthreads();

    const int p  = tid >> 4;             // slot 0..17
    const int q  = tid & 15;             // column quarter 0..15
    const int pp = min(p, 16);           // slot 17 duplicates 16
    const int base = blockIdx.x * PPB;
    const int kc = min(base + pp, TAB_ENTRIES);

    const float d2   = __int_as_float(TAB_BASE + (kc << TAB_SHIFT));
    const float dist = sqrtf(d2);
    const float invc = 1.0f / (d2 * dist);

    // phase 1: h1 for this point's a-range [q*4, q*4+4)
    if (p < 17) {
        const int a0 = q * 4;
        float4 h;
        h.x = fmaxf(fmaf(dist, sW1a[a0 + 0], fmaf(invc, sW1b[a0 + 0], sb1[a0 + 0])), 0.0f);
        h.y = fmaxf(fmaf(dist, sW1a[a0 + 1], fmaf(invc, sW1b[a0 + 1], sb1[a0 + 1])), 0.0f);
        h.z = fmaxf(fmaf(dist, sW1a[a0 + 2], fmaf(invc, sW1b[a0 + 2], sb1[a0 + 2])), 0.0f);
        h.w = fmaxf(fmaf(dist, sW1a[a0 + 3], fmaf(invc, sW1b[a0 + 3], sb1[a0 + 3])), 0.0f);
        *(float4*)&sh1[p][a0] = h;
    }
    __syncthreads();

    // phase 2: GEMV slice, columns [c0, c0+4)
    const int c0 = q * 4;
    float ax = 0.f, ay = 0.f, az = 0.f, aw = 0.f;
#pragma unroll 8
    for (int a = 0; a < HN; a++) {
        float h = sh1[pp][a];
        float4 w = *(const float4*)&sW2[a * HN + c0];
        ax = fmaf(h, w.x, ax);
        ay = fmaf(h, w.y, ay);
        az = fmaf(h, w.z, az);
        aw = fmaf(h, w.w, aw);
    }

    // phase 3: bias + relu + W3 dot, reduce over 16 lanes
    float m = fmaxf(ax + sb2[c0 + 0], 0.0f) * sW3[c0 + 0]
            + fmaxf(ay + sb2[c0 + 1], 0.0f) * sW3[c0 + 1]
            + fmaxf(az + sb2[c0 + 2], 0.0f) * sW3[c0 + 2]
            + fmaxf(aw + sb2[c0 + 3], 0.0f) * sW3[c0 + 3];
    m += __shfl_xor_sync(0xffffffffu, m, 1);
    m += __shfl_xor_sync(0xffffffffu, m, 2);
    m += __shfl_xor_sync(0xffffffffu, m, 4);
    m += __shfl_xor_sync(0xffffffffu, m, 8);

    if (q == 0 && p < 17)
        sm[p] = m + __ldg(b3);
    __syncthreads();

    // phase 4: pack 16 entries of this block
    if (tid < PPB) {
        int e = base + tid;
        if (e < TAB_ENTRIES) {
            float x0 = __int_as_float(TAB_BASE + (e << TAB_SHIFT));
            float x1 = __int_as_float(TAB_BASE + ((e + 1) << TAB_SHIFT));
            float v0 = sm[tid];
            float v1 = sm[tid + 1];
            float s  = (v1 - v0) / (x1 - x0);
            g_tab[e] = make_float2(fmaf(-x0, s, v0), s);   // m(d2) = c0 + d2*s
        }
    }
}

// ---------------------------------------------------------------------------
// Kernel 2: tiled all-pairs force accumulation.
//   acc_i = sum_j m(d2_ij) * (pos_j - pos_i)     (j==i term is exactly 0)
// JC=32 -> 2048 blocks -> ~55 warps/SM, AND the 6.5 KB table lives in smem:
// random LDS.64 gather (~5 bank phases) replaces divergent LDG (~15 L1
// wavefronts). 7 KB smem/block keeps 13.8 blocks/SM resident.
// ---------------------------------------------------------------------------
#define IT 128
#define JC 32

__global__ __launch_bounds__(IT)
void forces_kernel(const float* __restrict__ pos, float* __restrict__ out, int N)
{
    const int b  = blockIdx.z;
    const int i  = blockIdx.y * IT + threadIdx.x;
    const int j0 = blockIdx.x * JC;
    const float* p = pos + (size_t)b * N * 3;

    __shared__ float2 stab[TAB_ENTRIES];   // 6.5 KB
    __shared__ float4 sj[JC];

#pragma unroll
    for (int t = threadIdx.x; t < TAB_ENTRIES; t += IT)
        stab[t] = g_tab[t];
    if (threadIdx.x < JC) {
        int j = j0 + threadIdx.x;
        sj[threadIdx.x] = make_float4(p[j * 3 + 0], p[j * 3 + 1], p[j * 3 + 2], 0.0f);
    }
    __syncthreads();

    const float xi = p[i * 3 + 0];
    const float yi = p[i * 3 + 1];
    const float zi = p[i * 3 + 2];

    float ax = 0.0f, ay = 0.0f, az = 0.0f;

#pragma unroll
    for (int t = 0; t < JC; t++) {
        float4 pj = sj[t];
        float dx = pj.x - xi;
        float dy = pj.y - yi;
        float dz = pj.z - zi;
        float d2 = fmaf(dx, dx, fmaf(dy, dy, fmaf(dz, dz, EPS2f)));

        // d2 >= EPS^2 > table base, so only the upper clamp is needed
        int bits = min(__float_as_int(d2), (int)TAB_TOP - 1);
        float2 ts = stab[(unsigned)(bits - (int)TAB_BASE) >> TAB_SHIFT];
        float m = fmaf(d2, ts.y, ts.x);

        ax = fmaf(m, dx, ax);
        ay = fmaf(m, dy, ay);
        az = fmaf(m, dz, az);
    }

    float* o = out + ((size_t)b * N + i) * 3;
    atomicAdd(o + 0, ax);
    atomicAdd(o + 1, ay);
    atomicAdd(o + 2, az);
}

// ---------------------------------------------------------------------------
// Launch
// ---------------------------------------------------------------------------
extern "C" void kernel_launch(void* const* d_in, const int* in_sizes, int n_in,
                              void* d_out, int out_size)
{
    const float* pos = (const float*)d_in[0];
    const float* W1  = (const float*)d_in[1];
    const float* b1  = (const float*)d_in[2];
    const float* W2  = (const float*)d_in[3];
    const float* b2  = (const float*)d_in[4];
    const float* W3  = (const float*)d_in[5];
    const float* b3  = (const float*)d_in[6];
    float* out = (float*)d_out;

    const int N = 2048;
    const int B = in_sizes[0] / (N * 3);   // = 2

    // 1) build m(d2) table + pack (intercept, slope) + zero output, one kernel
    {
        int blocks = (TAB_ENTRIES + PPB - 1) / PPB;   // 51
        build_table_kernel<<<blocks, BT>>>(W1, b1, W2, b2, W3, b3, out, out_size);
    }
    // 2) main all-pairs accumulation
    {
        dim3 grid(N / JC, N / IT, B);
        forces_kernel<<<grid, IT>>>(pos, out, N);
    }
}